// round 2
// baseline (speedup 1.0000x reference)
#include <cuda_runtime.h>
#include <cstdint>

#define L_LAYERS 13
#define BATCH    32
#define SEQ      512
#define HID      768
#define QLEN     20
#define DLEN     492          // SEQ - QLEN
#define NKER     11
#define EPS_N    1e-8f

#define KC       32           // k-slice per stage
#define NSTAGE   (HID / KC)   // 24
#define DPAD     36           // padded row length (floats) -> conflict-free, 16B aligned
#define DROWS    512
#define QSM_ELT  (HID * QLEN)        // 15360 floats (Q transposed [k][q])
#define DBUF_ELT (DROWS * DPAD)      // 18432 floats per buffer
#define SMEM_BYTES ((QSM_ELT + 2 * DBUF_ELT) * 4)   // 61440 + 147456 = 208896 B

// pooled[l][b][m] scratch (static device global: no allocation allowed)
__device__ float g_pooled[L_LAYERS * BATCH * NKER];

__device__ __forceinline__ uint32_t smaddr(const void* p) {
    uint32_t r;
    asm("{ .reg .u64 t; cvta.to.shared.u64 t, %1; cvt.u32.u64 %0, t; }"
        : "=r"(r) : "l"(p));
    return r;
}
__device__ __forceinline__ void cp16(uint32_t dst, const float* src) {
    asm volatile("cp.async.cg.shared.global [%0], [%1], 16;"
                 :: "r"(dst), "l"(__cvta_generic_to_global(src)));
}

__global__ void __launch_bounds__(256, 1)
knrm_kernel(const float* __restrict__ hs,
            const float* __restrict__ mu,
            const float* __restrict__ sigma)
{
    extern __shared__ float sm[];
    float* qsT  = sm;               // [HID][QLEN]  (k-major, broadcast reads)
    float* dbuf = sm + QSM_ELT;     // [2][DROWS][DPAD]

    __shared__ float qinv[QLEN];
    __shared__ float mu_s[NKER], cf_s[NKER];
    __shared__ float spool[NKER];

    const int t = threadIdx.x;
    const int b = blockIdx.x;
    const int l = blockIdx.y;

    const float* base = hs + (size_t)(l * BATCH + b) * SEQ * HID;
    const float* qg   = base;             // tokens [0,20)
    const float* dg   = base + QLEN * HID; // tokens [20,512)

    if (t < NKER) {
        mu_s[t] = mu[t];
        float sg = sigma[t];
        cf_s[t] = -0.5f / (sg * sg);
        spool[t] = 0.f;
    }

    // ---- stage Q (fp32, transposed) ----
    for (int idx = t; idx < QLEN * (HID / 4); idx += 256) {
        int row = idx / (HID / 4);
        int k4  = idx % (HID / 4);
        float4 v = *(const float4*)(qg + row * HID + k4 * 4);
        qsT[(k4 * 4 + 0) * QLEN + row] = v.x;
        qsT[(k4 * 4 + 1) * QLEN + row] = v.y;
        qsT[(k4 * 4 + 2) * QLEN + row] = v.z;
        qsT[(k4 * 4 + 3) * QLEN + row] = v.w;
    }

    // ---- prefetch D stage 0 via cp.async ----
    uint32_t dsm = smaddr(dbuf);
    for (int idx = t; idx < DLEN * (KC / 4); idx += 256) {
        int tok = idx >> 3;
        int kq  = idx & 7;
        cp16(dsm + (uint32_t)(tok * DPAD + kq * 4) * 4,
             dg + (size_t)tok * HID + kq * 4);
    }
    asm volatile("cp.async.commit_group;");

    __syncthreads();   // qsT visible

    // ---- q inverse norms (one warp per set of rows) ----
    {
        int w = t >> 5, lane = t & 31;
        for (int r = w; r < QLEN; r += 8) {
            float s = 0.f;
            for (int k = lane; k < HID; k += 32) {
                float v = qsT[k * QLEN + r];
                s = fmaf(v, v, s);
            }
            #pragma unroll
            for (int off = 16; off; off >>= 1)
                s += __shfl_down_sync(0xffffffffu, s, off);
            if (lane == 0) qinv[r] = 1.f / fmaxf(sqrtf(s), EPS_N);
        }
    }

    // ---- mainloop: each thread owns d-tokens {t, t+256}, all 20 q rows ----
    float acc0[QLEN], acc1[QLEN];
    #pragma unroll
    for (int q = 0; q < QLEN; q++) { acc0[q] = 0.f; acc1[q] = 0.f; }
    float ds0 = 0.f, ds1 = 0.f;

    for (int s = 0; s < NSTAGE; s++) {
        if (s + 1 < NSTAGE) {
            uint32_t dstb = dsm + (uint32_t)(((s + 1) & 1) * DBUF_ELT) * 4;
            int k0n = (s + 1) * KC;
            for (int idx = t; idx < DLEN * (KC / 4); idx += 256) {
                int tok = idx >> 3;
                int kq  = idx & 7;
                cp16(dstb + (uint32_t)(tok * DPAD + kq * 4) * 4,
                     dg + (size_t)tok * HID + k0n + kq * 4);
            }
            asm volatile("cp.async.commit_group;");
            asm volatile("cp.async.wait_group 1;");
        } else {
            asm volatile("cp.async.wait_group 0;");
        }
        __syncthreads();   // stage s data visible to all

        const float* db  = dbuf + (s & 1) * DBUF_ELT;
        const float* d0p = db + t * DPAD;
        const float* d1p = db + (t + 256) * DPAD;
        const float* qk  = qsT + s * KC * QLEN;

        #pragma unroll 2
        for (int k4 = 0; k4 < KC / 4; k4++) {
            float4 dv0 = *(const float4*)(d0p + k4 * 4);
            float4 dv1 = *(const float4*)(d1p + k4 * 4);
            #pragma unroll
            for (int e = 0; e < 4; e++) {
                float d0 = (e == 0) ? dv0.x : (e == 1) ? dv0.y : (e == 2) ? dv0.z : dv0.w;
                float d1 = (e == 0) ? dv1.x : (e == 1) ? dv1.y : (e == 2) ? dv1.z : dv1.w;
                const float4* q4 = (const float4*)(qk + (k4 * 4 + e) * QLEN);
                float4 qa = q4[0], qb = q4[1], qc = q4[2], qd = q4[3], qe = q4[4];
                float qv[QLEN] = { qa.x, qa.y, qa.z, qa.w,
                                   qb.x, qb.y, qb.z, qb.w,
                                   qc.x, qc.y, qc.z, qc.w,
                                   qd.x, qd.y, qd.z, qd.w,
                                   qe.x, qe.y, qe.z, qe.w };
                #pragma unroll
                for (int q = 0; q < QLEN; q++) {
                    acc0[q] = fmaf(qv[q], d0, acc0[q]);
                    acc1[q] = fmaf(qv[q], d1, acc1[q]);
                }
                ds0 = fmaf(d0, d0, ds0);
                ds1 = fmaf(d1, d1, ds1);
            }
        }
        __syncthreads();   // done reading buffer before it is refilled
    }

    // ---- tail: gaussian kernels + pooling ----
    float p[NKER];
    #pragma unroll
    for (int m = 0; m < NKER; m++) p[m] = 0.f;

    float mur[NKER], cfr[NKER];
    #pragma unroll
    for (int m = 0; m < NKER; m++) { mur[m] = mu_s[m]; cfr[m] = cf_s[m]; }

    {
        float dinv = 1.f / fmaxf(sqrtf(ds0), EPS_N);
        #pragma unroll
        for (int q = 0; q < QLEN; q++) {
            float simv = acc0[q] * qinv[q] * dinv;
            #pragma unroll
            for (int m = 0; m < NKER; m++) {
                float dlt = simv - mur[m];
                p[m] += __expf(cfr[m] * dlt * dlt);
            }
        }
    }
    if (t < DLEN - 256) {   // second d-token valid only for t < 236
        float dinv = 1.f / fmaxf(sqrtf(ds1), EPS_N);
        #pragma unroll
        for (int q = 0; q < QLEN; q++) {
            float simv = acc1[q] * qinv[q] * dinv;
            #pragma unroll
            for (int m = 0; m < NKER; m++) {
                float dlt = simv - mur[m];
                p[m] += __expf(cfr[m] * dlt * dlt);
            }
        }
    }

    // warp reduce then smem atomic
    #pragma unroll
    for (int m = 0; m < NKER; m++) {
        float v = p[m];
        #pragma unroll
        for (int off = 16; off; off >>= 1)
            v += __shfl_down_sync(0xffffffffu, v, off);
        if ((t & 31) == 0) atomicAdd(&spool[m], v);
    }
    __syncthreads();
    if (t < NKER)
        g_pooled[(size_t)(l * BATCH + b) * NKER + t] = spool[t];
}

// ---- final combine: out[b] = cls . W[:768] + kf . W[768:] + bias ----
__global__ void combine_kernel(const float* __restrict__ hs,
                               const float* __restrict__ W,
                               const float* __restrict__ bC,
                               float* __restrict__ out)
{
    __shared__ float red[128];
    int b = blockIdx.x, t = threadIdx.x;
    const float* cls = hs + (size_t)((L_LAYERS - 1) * BATCH + b) * SEQ * HID; // token 0
    float s = 0.f;
    for (int f = t; f < HID; f += 128)
        s = fmaf(cls[f], W[f], s);
    for (int f = t; f < (L_LAYERS + 1) * NKER; f += 128) {
        int la = f / NKER;
        int m  = f - la * NKER;
        int cl = (la == 0) ? 0 : la - 1;   // all_layers[0] == hidden_states[0]
        s = fmaf(g_pooled[(size_t)(cl * BATCH + b) * NKER + m], W[HID + f], s);
    }
    red[t] = s;
    __syncthreads();
    #pragma unroll
    for (int st = 64; st; st >>= 1) {
        if (t < st) red[t] += red[t + st];
        __syncthreads();
    }
    if (t == 0) out[b] = red[0] + bC[0];
}

extern "C" void kernel_launch(void* const* d_in, const int* in_sizes, int n_in,
                              void* d_out, int out_size)
{
    const float* hs = (const float*)d_in[0];
    const float* mu = (const float*)d_in[1];
    const float* sg = (const float*)d_in[2];
    const float* W  = (const float*)d_in[3];
    const float* bC = (const float*)d_in[4];
    float* out = (float*)d_out;

    cudaFuncSetAttribute(knrm_kernel,
                         cudaFuncAttributeMaxDynamicSharedMemorySize, SMEM_BYTES);

    dim3 grid(BATCH, L_LAYERS);
    knrm_kernel<<<grid, 256, SMEM_BYTES>>>(hs, mu, sg);
    combine_kernel<<<BATCH, 128>>>(hs, W, bC, out);
}

// round 3
// speedup vs baseline: 1.1100x; 1.1100x over previous
#include <cuda_runtime.h>
#include <cstdint>

#define L_LAYERS 13
#define BATCH    32
#define SEQ      512
#define HID      768
#define QLEN     20
#define DLEN     492          // SEQ - QLEN
#define NKER     11
#define EPS_N    1e-8f

#define KC       32           // k-slice per stage
#define NSTAGE   (HID / KC)   // 24
#define DPAD     36           // padded row length (floats) -> conflict-free, 16B aligned
#define DROWS    512
#define QSM_ELT  (HID * QLEN)        // 15360 floats (Q transposed [k][q])
#define DBUF_ELT (DROWS * DPAD)      // 18432 floats per buffer
#define SMEM_BYTES ((QSM_ELT + 2 * DBUF_ELT) * 4)   // 61440 + 147456 = 208896 B

// pooled[l][b][m] scratch (static device global: no allocation allowed)
__device__ float g_pooled[L_LAYERS * BATCH * NKER];

__device__ __forceinline__ uint32_t smaddr(const void* p) {
    uint32_t r;
    asm("{ .reg .u64 t; cvta.to.shared.u64 t, %1; cvt.u32.u64 %0, t; }"
        : "=r"(r) : "l"(p));
    return r;
}
__device__ __forceinline__ void cp16(uint32_t dst, const float* src) {
    asm volatile("cp.async.cg.shared.global [%0], [%1], 16;"
                 :: "r"(dst), "l"(__cvta_generic_to_global(src)));
}

// ---- packed f32x2 helpers (Blackwell FFMA2 path, PTX-only) ----
__device__ __forceinline__ unsigned long long pack2(float lo, float hi) {
    unsigned long long r;
    asm("mov.b64 %0, {%1, %2};" : "=l"(r) : "f"(lo), "f"(hi));
    return r;
}
__device__ __forceinline__ void fma2(unsigned long long& acc,
                                     unsigned long long a,
                                     unsigned long long b) {
    asm("fma.rn.f32x2 %0, %1, %2, %0;" : "+l"(acc) : "l"(a), "l"(b));
}
__device__ __forceinline__ void unpack2(unsigned long long v, float& lo, float& hi) {
    asm("mov.b64 {%0, %1}, %2;" : "=f"(lo), "=f"(hi) : "l"(v));
}

__global__ void __launch_bounds__(256, 1)
knrm_kernel(const float* __restrict__ hs,
            const float* __restrict__ mu,
            const float* __restrict__ sigma)
{
    extern __shared__ float sm[];
    float* qsT  = sm;               // [HID][QLEN]  (k-major, broadcast reads)
    float* dbuf = sm + QSM_ELT;     // [2][DROWS][DPAD]

    __shared__ float qinv[QLEN];
    __shared__ float mu_s[NKER], cf_s[NKER];
    __shared__ float spool[NKER];

    const int t = threadIdx.x;
    const int b = blockIdx.x;
    const int l = blockIdx.y;

    const float* base = hs + (size_t)(l * BATCH + b) * SEQ * HID;
    const float* qg   = base;              // tokens [0,20)
    const float* dg   = base + QLEN * HID; // tokens [20,512)

    if (t < NKER) {
        mu_s[t] = mu[t];
        float sg = sigma[t];
        cf_s[t] = -0.5f / (sg * sg);
        spool[t] = 0.f;
    }

    // ---- stage Q (fp32, transposed, k-major) ----
    for (int idx = t; idx < QLEN * (HID / 4); idx += 256) {
        int row = idx / (HID / 4);
        int k4  = idx % (HID / 4);
        float4 v = *(const float4*)(qg + row * HID + k4 * 4);
        qsT[(k4 * 4 + 0) * QLEN + row] = v.x;
        qsT[(k4 * 4 + 1) * QLEN + row] = v.y;
        qsT[(k4 * 4 + 2) * QLEN + row] = v.z;
        qsT[(k4 * 4 + 3) * QLEN + row] = v.w;
    }

    // ---- prefetch D stage 0 via cp.async ----
    uint32_t dsm = smaddr(dbuf);
    for (int idx = t; idx < DLEN * (KC / 4); idx += 256) {
        int tok = idx >> 3;
        int kq  = idx & 7;
        cp16(dsm + (uint32_t)(tok * DPAD + kq * 4) * 4,
             dg + (size_t)tok * HID + kq * 4);
    }
    asm volatile("cp.async.commit_group;");

    __syncthreads();   // qsT visible

    // ---- q inverse norms ----
    {
        int w = t >> 5, lane = t & 31;
        for (int r = w; r < QLEN; r += 8) {
            float s = 0.f;
            for (int k = lane; k < HID; k += 32) {
                float v = qsT[k * QLEN + r];
                s = fmaf(v, v, s);
            }
            #pragma unroll
            for (int off = 16; off; off >>= 1)
                s += __shfl_down_sync(0xffffffffu, s, off);
            if (lane == 0) qinv[r] = 1.f / fmaxf(sqrtf(s), EPS_N);
        }
    }

    // ---- mainloop: packed f32x2 accumulators over q-pairs ----
    // accp0[j] = (acc[2j], acc[2j+1]) for d-token t; accp1 for d-token t+256.
    unsigned long long accp0[QLEN / 2], accp1[QLEN / 2];
    #pragma unroll
    for (int j = 0; j < QLEN / 2; j++) { accp0[j] = 0ull; accp1[j] = 0ull; }
    unsigned long long dsp = 0ull;   // (ds0, ds1) packed

    for (int s = 0; s < NSTAGE; s++) {
        if (s + 1 < NSTAGE) {
            uint32_t dstb = dsm + (uint32_t)(((s + 1) & 1) * DBUF_ELT) * 4;
            int k0n = (s + 1) * KC;
            for (int idx = t; idx < DLEN * (KC / 4); idx += 256) {
                int tok = idx >> 3;
                int kq  = idx & 7;
                cp16(dstb + (uint32_t)(tok * DPAD + kq * 4) * 4,
                     dg + (size_t)tok * HID + k0n + kq * 4);
            }
            asm volatile("cp.async.commit_group;");
            asm volatile("cp.async.wait_group 1;");
        } else {
            asm volatile("cp.async.wait_group 0;");
        }
        __syncthreads();   // stage s data visible

        const float* db  = dbuf + (s & 1) * DBUF_ELT;
        const float* d0p = db + t * DPAD;
        const float* d1p = db + (t + 256) * DPAD;
        const float* qk  = qsT + s * KC * QLEN;

        #pragma unroll 2
        for (int k4 = 0; k4 < KC / 4; k4++) {
            float4 dv0 = *(const float4*)(d0p + k4 * 4);
            float4 dv1 = *(const float4*)(d1p + k4 * 4);
            #pragma unroll
            for (int e = 0; e < 4; e++) {
                float d0 = (e == 0) ? dv0.x : (e == 1) ? dv0.y : (e == 2) ? dv0.z : dv0.w;
                float d1 = (e == 0) ? dv1.x : (e == 1) ? dv1.y : (e == 2) ? dv1.z : dv1.w;
                unsigned long long d00 = pack2(d0, d0);
                unsigned long long d11 = pack2(d1, d1);
                unsigned long long d01 = pack2(d0, d1);

                // q row: 20 floats = 5 x 16B, ulonglong2 loads give packed q-pairs
                const ulonglong2* q16 = (const ulonglong2*)(qk + (k4 * 4 + e) * QLEN);
                ulonglong2 qa = q16[0], qb = q16[1];
                unsigned long long q8 = ((const unsigned long long*)q16)[4];
                // wait, row = 20 floats = 2.5 x ulonglong2; handle 4 + 1:
                ulonglong2 qc = q16[2];
                ulonglong2 qd_dummy; (void)qd_dummy; (void)q8;
                // pairs: qa.x qa.y qb.x qb.y qc.x qc.y + 4 more from next 16B
                const unsigned long long* qp = (const unsigned long long*)q16;
                unsigned long long q6 = qp[6], q7 = qp[7], q8b = qp[8], q9 = qp[9];

                fma2(accp0[0], qa.x, d00);  fma2(accp1[0], qa.x, d11);
                fma2(accp0[1], qa.y, d00);  fma2(accp1[1], qa.y, d11);
                fma2(accp0[2], qb.x, d00);  fma2(accp1[2], qb.x, d11);
                fma2(accp0[3], qb.y, d00);  fma2(accp1[3], qb.y, d11);
                fma2(accp0[4], qc.x, d00);  fma2(accp1[4], qc.x, d11);
                fma2(accp0[5], qc.y, d00);  fma2(accp1[5], qc.y, d11);
                fma2(accp0[6], q6,   d00);  fma2(accp1[6], q6,   d11);
                fma2(accp0[7], q7,   d00);  fma2(accp1[7], q7,   d11);
                fma2(accp0[8], q8b,  d00);  fma2(accp1[8], q8b,  d11);
                fma2(accp0[9], q9,   d00);  fma2(accp1[9], q9,   d11);
                fma2(dsp, d01, d01);
            }
        }
        __syncthreads();   // done reading buffer before refill
    }

    // ---- unpack accumulators ----
    float acc0[QLEN], acc1[QLEN];
    #pragma unroll
    for (int j = 0; j < QLEN / 2; j++) {
        unpack2(accp0[j], acc0[2 * j], acc0[2 * j + 1]);
        unpack2(accp1[j], acc1[2 * j], acc1[2 * j + 1]);
    }
    float ds0, ds1;
    unpack2(dsp, ds0, ds1);

    // ---- tail: gaussian kernels + pooling ----
    float p[NKER];
    #pragma unroll
    for (int m = 0; m < NKER; m++) p[m] = 0.f;

    float mur[NKER], cfr[NKER];
    #pragma unroll
    for (int m = 0; m < NKER; m++) { mur[m] = mu_s[m]; cfr[m] = cf_s[m]; }

    {
        float dinv = 1.f / fmaxf(sqrtf(ds0), EPS_N);
        #pragma unroll
        for (int q = 0; q < QLEN; q++) {
            float simv = acc0[q] * qinv[q] * dinv;
            #pragma unroll
            for (int m = 0; m < NKER; m++) {
                float dlt = simv - mur[m];
                p[m] += __expf(cfr[m] * dlt * dlt);
            }
        }
    }
    if (t < DLEN - 256) {   // second d-token valid only for t < 236
        float dinv = 1.f / fmaxf(sqrtf(ds1), EPS_N);
        #pragma unroll
        for (int q = 0; q < QLEN; q++) {
            float simv = acc1[q] * qinv[q] * dinv;
            #pragma unroll
            for (int m = 0; m < NKER; m++) {
                float dlt = simv - mur[m];
                p[m] += __expf(cfr[m] * dlt * dlt);
            }
        }
    }

    // warp reduce then smem atomic
    #pragma unroll
    for (int m = 0; m < NKER; m++) {
        float v = p[m];
        #pragma unroll
        for (int off = 16; off; off >>= 1)
            v += __shfl_down_sync(0xffffffffu, v, off);
        if ((t & 31) == 0) atomicAdd(&spool[m], v);
    }
    __syncthreads();
    if (t < NKER)
        g_pooled[(size_t)(l * BATCH + b) * NKER + t] = spool[t];
}

// ---- final combine: out[b] = cls . W[:768] + kf . W[768:] + bias ----
__global__ void combine_kernel(const float* __restrict__ hs,
                               const float* __restrict__ W,
                               const float* __restrict__ bC,
                               float* __restrict__ out)
{
    __shared__ float red[128];
    int b = blockIdx.x, t = threadIdx.x;
    const float* cls = hs + (size_t)((L_LAYERS - 1) * BATCH + b) * SEQ * HID; // token 0
    float s = 0.f;
    for (int f = t; f < HID; f += 128)
        s = fmaf(cls[f], W[f], s);
    for (int f = t; f < (L_LAYERS + 1) * NKER; f += 128) {
        int la = f / NKER;
        int m  = f - la * NKER;
        int cl = (la == 0) ? 0 : la - 1;   // all_layers[0] == hidden_states[0]
        s = fmaf(g_pooled[(size_t)(cl * BATCH + b) * NKER + m], W[HID + f], s);
    }
    red[t] = s;
    __syncthreads();
    #pragma unroll
    for (int st = 64; st; st >>= 1) {
        if (t < st) red[t] += red[t + st];
        __syncthreads();
    }
    if (t == 0) out[b] = red[0] + bC[0];
}

extern "C" void kernel_launch(void* const* d_in, const int* in_sizes, int n_in,
                              void* d_out, int out_size)
{
    const float* hs = (const float*)d_in[0];
    const float* mu = (const float*)d_in[1];
    const float* sg = (const float*)d_in[2];
    const float* W  = (const float*)d_in[3];
    const float* bC = (const float*)d_in[4];
    float* out = (float*)d_out;

    cudaFuncSetAttribute(knrm_kernel,
                         cudaFuncAttributeMaxDynamicSharedMemorySize, SMEM_BYTES);

    dim3 grid(BATCH, L_LAYERS);
    knrm_kernel<<<grid, 256, SMEM_BYTES>>>(hs, mu, sg);
    combine_kernel<<<BATCH, 128>>>(hs, W, bC, out);
}

// round 4
// speedup vs baseline: 1.3467x; 1.2133x over previous
#include <cuda_runtime.h>
#include <cstdint>

#define L_LAYERS 13
#define BATCH    32
#define SEQ      512
#define HID      768
#define QLEN     20
#define DLEN     492          // SEQ - QLEN
#define NKER     11
#define EPS_N    1e-8f

#define KC       16           // k-slice per D stage
#define NSTAGE   (HID / KC)   // 48
#define DPAD     20           // padded D row (floats): banks 20g+c = 4g+c conflict-free
#define DROWS    512          // padded token count (492 real)
#define QPAD     40           // padded Q-col dim: banks 8k+q conflict-free for frags
#define QSM_ELT  (HID * QPAD)        // 30720 words (tf32 Q, k-major)
#define DBUF_ELT (DROWS * DPAD)      // 10240 words per buffer
#define SMEM_BYTES ((QSM_ELT + 2 * DBUF_ELT) * 4)   // 204800 B

__device__ float g_pooled[L_LAYERS * BATCH * NKER];

__device__ __forceinline__ uint32_t smaddr(const void* p) {
    uint32_t r;
    asm("{ .reg .u64 t; cvta.to.shared.u64 t, %1; cvt.u32.u64 %0, t; }"
        : "=r"(r) : "l"(p));
    return r;
}
__device__ __forceinline__ void cp16(uint32_t dst, const float* src) {
    asm volatile("cp.async.cg.shared.global [%0], [%1], 16;"
                 :: "r"(dst), "l"(__cvta_generic_to_global(src)));
}
__device__ __forceinline__ uint32_t f2tf32(float v) {
    uint32_t r;
    asm("cvt.rna.tf32.f32 %0, %1;" : "=r"(r) : "f"(v));
    return r;
}
__device__ __forceinline__ void mma_tf32(float* c, const uint32_t* a,
                                         uint32_t b0, uint32_t b1) {
    asm volatile(
        "mma.sync.aligned.m16n8k8.row.col.f32.tf32.tf32.f32 "
        "{%0,%1,%2,%3}, {%4,%5,%6,%7}, {%8,%9}, {%0,%1,%2,%3};"
        : "+f"(c[0]), "+f"(c[1]), "+f"(c[2]), "+f"(c[3])
        : "r"(a[0]), "r"(a[1]), "r"(a[2]), "r"(a[3]), "r"(b0), "r"(b1));
}

__global__ void __launch_bounds__(256, 1)
knrm_kernel(const float* __restrict__ hs,
            const float* __restrict__ mu,
            const float* __restrict__ sigma)
{
    extern __shared__ float sm[];
    uint32_t* qsTu = (uint32_t*)sm;        // [HID][QPAD] tf32, k-major
    float*    dbuf = sm + QSM_ELT;         // [2][DROWS][DPAD] fp32

    __shared__ float qinv[QLEN];
    __shared__ float dinv_s[DROWS];
    __shared__ float mu_s[NKER], cf_s[NKER];
    __shared__ float spool[NKER];

    const int t  = threadIdx.x;
    const int b  = blockIdx.x;
    const int l  = blockIdx.y;
    const int ln = t & 31;
    const int gr = ln >> 2;        // fragment group (0..7)
    const int c  = ln & 3;         // thread-in-group (0..3)
    const int wbase = (t >> 5) * 64;   // this warp's token base (0..448)

    const float* base = hs + (size_t)(l * BATCH + b) * SEQ * HID;
    const float* qg   = base;              // tokens [0,20)
    const float* dg   = base + QLEN * HID; // tokens [20,512)

    if (t < NKER) {
        mu_s[t] = mu[t];
        float sg = sigma[t];
        cf_s[t] = -0.5f / (sg * sg);
        spool[t] = 0.f;
    }

    // ---- stage Q -> tf32, k-major [k][QPAD], rows >=20 zeroed ----
    // warp-iter: 8 q-rows x 16 k; rotated component stores => conflict-free STS
    {
        int qb = ln >> 2;      // q sub-row 0..7
        int kb = ln & 3;       // k float4 index 0..3
        for (int it = (t >> 5); it < 4 * (HID / 16); it += 8) {
            int qblk = it / (HID / 16);       // 0..3
            int kblk = it % (HID / 16);       // 0..47
            int q  = qblk * 8 + qb;           // 0..31
            int k0 = kblk * 16;
            float4 v = (q < QLEN)
                ? *(const float4*)(qg + q * HID + k0 + kb * 4)
                : make_float4(0.f, 0.f, 0.f, 0.f);
            float vv[4] = {v.x, v.y, v.z, v.w};
            #pragma unroll
            for (int j = 0; j < 4; j++) {
                int e = (j + kb) & 3;
                int k = k0 + kb * 4 + e;
                qsTu[k * QPAD + q] = f2tf32(vv[e]);
            }
        }
    }

    // ---- prefetch D stage 0 ----
    uint32_t dsm = smaddr(dbuf);
    for (int idx = t; idx < DLEN * 4; idx += 256) {
        int tok = idx >> 2, kq = idx & 3;
        cp16(dsm + (uint32_t)(tok * DPAD + kq * 4) * 4,
             dg + (size_t)tok * HID + kq * 4);
    }
    asm volatile("cp.async.commit_group;");

    // ---- q inverse norms (exact fp32, from global; L2-hot) ----
    {
        int w = t >> 5, lane = ln;
        for (int r = w; r < QLEN; r += 8) {
            float s = 0.f;
            for (int k = lane; k < HID; k += 32) {
                float v = qg[r * HID + k];
                s = fmaf(v, v, s);
            }
            #pragma unroll
            for (int off = 16; off; off >>= 1)
                s += __shfl_down_sync(0xffffffffu, s, off);
            if (lane == 0) qinv[r] = 1.f / fmaxf(sqrtf(s), EPS_N);
        }
    }
    __syncthreads();   // qsTu + qinv visible

    // ---- mainloop: tf32 mma, warp owns 64 d-tokens x all 32 q rows ----
    float acc[2][8][4];
    #pragma unroll
    for (int mt = 0; mt < 2; mt++)
        #pragma unroll
        for (int nt = 0; nt < 8; nt++)
            #pragma unroll
            for (int e = 0; e < 4; e++) acc[mt][nt][e] = 0.f;
    float ds[8];
    #pragma unroll
    for (int nt = 0; nt < 8; nt++) ds[nt] = 0.f;

    for (int s = 0; s < NSTAGE; s++) {
        if (s + 1 < NSTAGE) {
            uint32_t dstb = dsm + (uint32_t)(((s + 1) & 1) * DBUF_ELT) * 4;
            int kg = (s + 1) * KC;
            for (int idx = t; idx < DLEN * 4; idx += 256) {
                int tok = idx >> 2, kq = idx & 3;
                cp16(dstb + (uint32_t)(tok * DPAD + kq * 4) * 4,
                     dg + (size_t)tok * HID + kg + kq * 4);
            }
            asm volatile("cp.async.commit_group;");
            asm volatile("cp.async.wait_group 1;");
        } else {
            asm volatile("cp.async.wait_group 0;");
        }
        __syncthreads();

        const float* db = dbuf + (s & 1) * DBUF_ELT;

        #pragma unroll
        for (int step = 0; step < 2; step++) {
            const int kk = s * KC + step * 8;   // global k base of this k8

            uint32_t a[2][4];
            #pragma unroll
            for (int mt = 0; mt < 2; mt++) {
                int r0 = mt * 16 + gr;
                a[mt][0] = qsTu[(kk + c)     * QPAD + r0];
                a[mt][1] = qsTu[(kk + c)     * QPAD + r0 + 8];
                a[mt][2] = qsTu[(kk + c + 4) * QPAD + r0];
                a[mt][3] = qsTu[(kk + c + 4) * QPAD + r0 + 8];
            }

            #pragma unroll
            for (int nt = 0; nt < 8; nt++) {
                const float* dp = db + (wbase + nt * 8 + gr) * DPAD + step * 8;
                float f0 = dp[c];
                float f1 = dp[c + 4];
                ds[nt] = fmaf(f0, f0, fmaf(f1, f1, ds[nt]));
                uint32_t b0 = __float_as_uint(f0);   // tf32 by truncation
                uint32_t b1 = __float_as_uint(f1);
                mma_tf32(acc[0][nt], a[0], b0, b1);
                mma_tf32(acc[1][nt], a[1], b0, b1);
            }
        }
        __syncthreads();
    }

    // ---- d inverse norms: reduce over the 4 lanes of each quad (c dim) ----
    #pragma unroll
    for (int nt = 0; nt < 8; nt++) {
        float v = ds[nt];
        v += __shfl_xor_sync(0xffffffffu, v, 1);
        v += __shfl_xor_sync(0xffffffffu, v, 2);
        if (c == 0)
            dinv_s[wbase + nt * 8 + gr] = 1.f / fmaxf(sqrtf(v), EPS_N);
    }
    __syncwarp();

    // ---- Gaussian kernels + pooling ----
    float p[NKER];
    #pragma unroll
    for (int m = 0; m < NKER; m++) p[m] = 0.f;
    float mur[NKER], cfr[NKER];
    #pragma unroll
    for (int m = 0; m < NKER; m++) { mur[m] = mu_s[m]; cfr[m] = cf_s[m]; }

    #pragma unroll
    for (int mt = 0; mt < 2; mt++) {
        #pragma unroll
        for (int h = 0; h < 2; h++) {
            int m = mt * 16 + gr + h * 8;
            if (m < QLEN) {
                float qi = qinv[m];
                #pragma unroll
                for (int nt = 0; nt < 8; nt++) {
                    #pragma unroll
                    for (int col = 0; col < 2; col++) {
                        int tok = wbase + nt * 8 + 2 * c + col;
                        if (tok < DLEN) {
                            float simv = acc[mt][nt][h * 2 + col] * qi * dinv_s[tok];
                            #pragma unroll
                            for (int j = 0; j < NKER; j++) {
                                float dlt = simv - mur[j];
                                p[j] += __expf(cfr[j] * dlt * dlt);
                            }
                        }
                    }
                }
            }
        }
    }

    // warp reduce then smem atomic
    #pragma unroll
    for (int m = 0; m < NKER; m++) {
        float v = p[m];
        #pragma unroll
        for (int off = 16; off; off >>= 1)
            v += __shfl_down_sync(0xffffffffu, v, off);
        if (ln == 0) atomicAdd(&spool[m], v);
    }
    __syncthreads();
    if (t < NKER)
        g_pooled[(size_t)(l * BATCH + b) * NKER + t] = spool[t];
}

// ---- final combine: out[b] = cls . W[:768] + kf . W[768:] + bias ----
__global__ void combine_kernel(const float* __restrict__ hs,
                               const float* __restrict__ W,
                               const float* __restrict__ bC,
                               float* __restrict__ out)
{
    __shared__ float red[128];
    int b = blockIdx.x, t = threadIdx.x;
    const float* cls = hs + (size_t)((L_LAYERS - 1) * BATCH + b) * SEQ * HID; // token 0
    float s = 0.f;
    for (int f = t; f < HID; f += 128)
        s = fmaf(cls[f], W[f], s);
    for (int f = t; f < (L_LAYERS + 1) * NKER; f += 128) {
        int la = f / NKER;
        int m  = f - la * NKER;
        int cl = (la == 0) ? 0 : la - 1;   // all_layers[0] == hidden_states[0]
        s = fmaf(g_pooled[(size_t)(cl * BATCH + b) * NKER + m], W[HID + f], s);
    }
    red[t] = s;
    __syncthreads();
    #pragma unroll
    for (int st = 64; st; st >>= 1) {
        if (t < st) red[t] += red[t + st];
        __syncthreads();
    }
    if (t == 0) out[b] = red[0] + bC[0];
}

extern "C" void kernel_launch(void* const* d_in, const int* in_sizes, int n_in,
                              void* d_out, int out_size)
{
    const float* hs = (const float*)d_in[0];
    const float* mu = (const float*)d_in[1];
    const float* sg = (const float*)d_in[2];
    const float* W  = (const float*)d_in[3];
    const float* bC = (const float*)d_in[4];
    float* out = (float*)d_out;

    cudaFuncSetAttribute(knrm_kernel,
                         cudaFuncAttributeMaxDynamicSharedMemorySize, SMEM_BYTES);

    dim3 grid(BATCH, L_LAYERS);
    knrm_kernel<<<grid, 256, SMEM_BYTES>>>(hs, mu, sg);
    combine_kernel<<<BATCH, 128>>>(hs, W, bC, out);
}

// round 5
// speedup vs baseline: 1.4189x; 1.0536x over previous
#include <cuda_runtime.h>
#include <cstdint>

#define L_LAYERS 13
#define BATCH    32
#define SEQ      512
#define HID      768
#define QLEN     20
#define DLEN     492          // SEQ - QLEN
#define NKER     11
#define EPS_N    1e-8f

#define NTHR     512
#define KC       16           // k-slice per D stage
#define NSTAGE   (HID / KC)   // 48
#define NBUF     3            // pipeline depth
#define DPAD     20           // padded D row (floats): banks 20g+c conflict-free
#define DROWS    512          // padded token count (492 real)
#define KP       772          // Q row stride (772 mod 32 == 4 -> conflict-free frags)
#define QSM_ELT  (32 * KP)            // 24704 words (tf32 Q, row-major, rows>=20 zero)
#define DBUF_ELT (DROWS * DPAD)       // 10240 words per buffer
#define SMEM_BYTES ((QSM_ELT + NBUF * DBUF_ELT) * 4)   // 221696 B

__device__ float g_pooled[L_LAYERS * BATCH * NKER];

__device__ __forceinline__ uint32_t smaddr(const void* p) {
    uint32_t r;
    asm("{ .reg .u64 t; cvta.to.shared.u64 t, %1; cvt.u32.u64 %0, t; }"
        : "=r"(r) : "l"(p));
    return r;
}
__device__ __forceinline__ void cp16(uint32_t dst, const float* src) {
    asm volatile("cp.async.cg.shared.global [%0], [%1], 16;"
                 :: "r"(dst), "l"(__cvta_generic_to_global(src)));
}
__device__ __forceinline__ uint32_t f2tf32(float v) {
    uint32_t r;
    asm("cvt.rna.tf32.f32 %0, %1;" : "=r"(r) : "f"(v));
    return r;
}
__device__ __forceinline__ void mma_tf32(float* c, const uint32_t* a,
                                         uint32_t b0, uint32_t b1) {
    asm volatile(
        "mma.sync.aligned.m16n8k8.row.col.f32.tf32.tf32.f32 "
        "{%0,%1,%2,%3}, {%4,%5,%6,%7}, {%8,%9}, {%0,%1,%2,%3};"
        : "+f"(c[0]), "+f"(c[1]), "+f"(c[2]), "+f"(c[3])
        : "r"(a[0]), "r"(a[1]), "r"(a[2]), "r"(a[3]), "r"(b0), "r"(b1));
}

__global__ void __launch_bounds__(NTHR, 1)
knrm_kernel(const float* __restrict__ hs,
            const float* __restrict__ mu,
            const float* __restrict__ sigma)
{
    extern __shared__ float sm[];
    uint32_t* qs   = (uint32_t*)sm;        // [32][KP] tf32, row-major
    float*    dbuf = sm + QSM_ELT;         // [NBUF][DROWS][DPAD] fp32

    __shared__ float qinv[QLEN];
    __shared__ float dinv_s[DROWS];
    __shared__ float mu_s[NKER], cf_s[NKER];
    __shared__ float spool[NKER];

    const int t  = threadIdx.x;
    const int b  = blockIdx.x;
    const int l  = blockIdx.y;
    const int ln = t & 31;
    const int gr = ln >> 2;            // fragment group (0..7)
    const int c  = ln & 3;             // thread-in-group (0..3)
    const int wbase = (t >> 5) * 32;   // this warp's token base (0..480)

    const float* base = hs + (size_t)(l * BATCH + b) * SEQ * HID;
    const float* qg   = base;              // tokens [0,20)
    const float* dg   = base + QLEN * HID; // tokens [20,512)

    if (t < NKER) {
        mu_s[t] = mu[t];
        float sg = sigma[t];
        cf_s[t] = -0.5f / (sg * sg);
        spool[t] = 0.f;
    }

    // ---- zero D-buffer tail rows (tokens 492..511) ----
    for (int idx = t; idx < NBUF * (DROWS - DLEN) * DPAD; idx += NTHR) {
        int bb  = idx / ((DROWS - DLEN) * DPAD);
        int rem = idx % ((DROWS - DLEN) * DPAD);
        dbuf[bb * DBUF_ELT + DLEN * DPAD + rem] = 0.f;
    }

    // ---- stage Q -> tf32 row-major [32][KP], rows >= 20 zeroed ----
    for (int idx = t; idx < 32 * (HID / 4); idx += NTHR) {
        int row = idx / (HID / 4);
        int k4  = idx % (HID / 4);
        float4 v = (row < QLEN)
            ? *(const float4*)(qg + row * HID + k4 * 4)
            : make_float4(0.f, 0.f, 0.f, 0.f);
        uint32_t* dst = qs + row * KP + k4 * 4;
        dst[0] = f2tf32(v.x);
        dst[1] = f2tf32(v.y);
        dst[2] = f2tf32(v.z);
        dst[3] = f2tf32(v.w);
    }

    // ---- prefetch first NBUF D stages ----
    uint32_t dsm = smaddr(dbuf);
    #pragma unroll
    for (int ps = 0; ps < NBUF; ps++) {
        uint32_t dstb = dsm + (uint32_t)(ps * DBUF_ELT) * 4;
        int kg = ps * KC;
        for (int idx = t; idx < DLEN * 4; idx += NTHR) {
            int tok = idx >> 2, kq = idx & 3;
            cp16(dstb + (uint32_t)(tok * DPAD + kq * 4) * 4,
                 dg + (size_t)tok * HID + kg + kq * 4);
        }
        asm volatile("cp.async.commit_group;");
    }

    // ---- q inverse norms (exact fp32, from global; L2-hot) ----
    {
        int w = t >> 5;
        for (int r = w; r < QLEN; r += 16) {
            float s = 0.f;
            for (int k = ln; k < HID; k += 32) {
                float v = qg[r * HID + k];
                s = fmaf(v, v, s);
            }
            #pragma unroll
            for (int off = 16; off; off >>= 1)
                s += __shfl_down_sync(0xffffffffu, s, off);
            if (ln == 0) qinv[r] = 1.f / fmaxf(sqrtf(s), EPS_N);
        }
    }

    // ---- mainloop: tf32 mma, warp owns 32 d-tokens x all 32 q rows ----
    float acc[2][4][4];
    #pragma unroll
    for (int mt = 0; mt < 2; mt++)
        #pragma unroll
        for (int nt = 0; nt < 4; nt++)
            #pragma unroll
            for (int e = 0; e < 4; e++) acc[mt][nt][e] = 0.f;
    float ds[4];
    #pragma unroll
    for (int nt = 0; nt < 4; nt++) ds[nt] = 0.f;

    for (int s = 0; s < NSTAGE; s++) {
        asm volatile("cp.async.wait_group %0;" :: "n"(NBUF - 1));
        __syncthreads();   // buffer s visible to all (and prologue smem on s==0)

        const float* db = dbuf + (s % NBUF) * DBUF_ELT;

        #pragma unroll
        for (int step = 0; step < 2; step++) {
            const int kk = s * KC + step * 8;   // global k base of this k8

            uint32_t a[2][4];
            #pragma unroll
            for (int mt = 0; mt < 2; mt++) {
                int r0 = mt * 16 + gr;
                a[mt][0] = qs[ r0      * KP + kk + c];
                a[mt][1] = qs[(r0 + 8) * KP + kk + c];
                a[mt][2] = qs[ r0      * KP + kk + c + 4];
                a[mt][3] = qs[(r0 + 8) * KP + kk + c + 4];
            }

            #pragma unroll
            for (int nt = 0; nt < 4; nt++) {
                const float* dp = db + (wbase + nt * 8 + gr) * DPAD + step * 8;
                float f0 = dp[c];
                float f1 = dp[c + 4];
                ds[nt] = fmaf(f0, f0, fmaf(f1, f1, ds[nt]));
                uint32_t b0 = __float_as_uint(f0);   // tf32 by truncation
                uint32_t b1 = __float_as_uint(f1);
                mma_tf32(acc[0][nt], a[0], b0, b1);
                mma_tf32(acc[1][nt], a[1], b0, b1);
            }
        }
        __syncthreads();   // all done reading buf (s % NBUF) before refill

        // issue prefetch of stage s+NBUF into the buffer just released
        if (s + NBUF < NSTAGE) {
            uint32_t dstb = dsm + (uint32_t)(((s + NBUF) % NBUF) * DBUF_ELT) * 4;
            int kg = (s + NBUF) * KC;
            for (int idx = t; idx < DLEN * 4; idx += NTHR) {
                int tok = idx >> 2, kq = idx & 3;
                cp16(dstb + (uint32_t)(tok * DPAD + kq * 4) * 4,
                     dg + (size_t)tok * HID + kg + kq * 4);
            }
        }
        asm volatile("cp.async.commit_group;");   // always commit (maybe empty)
    }

    // ---- d inverse norms: reduce over the 4 lanes of each quad ----
    #pragma unroll
    for (int nt = 0; nt < 4; nt++) {
        float v = ds[nt];
        v += __shfl_xor_sync(0xffffffffu, v, 1);
        v += __shfl_xor_sync(0xffffffffu, v, 2);
        if (c == 0)
            dinv_s[wbase + nt * 8 + gr] = 1.f / fmaxf(sqrtf(v), EPS_N);
    }
    __syncwarp();

    // ---- Gaussian kernels + pooling ----
    float p[NKER];
    #pragma unroll
    for (int m = 0; m < NKER; m++) p[m] = 0.f;
    float mur[NKER], cfr[NKER];
    #pragma unroll
    for (int m = 0; m < NKER; m++) { mur[m] = mu_s[m]; cfr[m] = cf_s[m]; }

    #pragma unroll
    for (int mt = 0; mt < 2; mt++) {
        #pragma unroll
        for (int h = 0; h < 2; h++) {
            int m = mt * 16 + gr + h * 8;
            if (m < QLEN) {
                float qi = qinv[m];
                #pragma unroll
                for (int nt = 0; nt < 4; nt++) {
                    #pragma unroll
                    for (int col = 0; col < 2; col++) {
                        int tok = wbase + nt * 8 + 2 * c + col;
                        if (tok < DLEN) {
                            float simv = acc[mt][nt][h * 2 + col] * qi * dinv_s[tok];
                            #pragma unroll
                            for (int j = 0; j < NKER; j++) {
                                float dlt = simv - mur[j];
                                p[j] += __expf(cfr[j] * dlt * dlt);
                            }
                        }
                    }
                }
            }
        }
    }

    // warp reduce then smem atomic
    #pragma unroll
    for (int m = 0; m < NKER; m++) {
        float v = p[m];
        #pragma unroll
        for (int off = 16; off; off >>= 1)
            v += __shfl_down_sync(0xffffffffu, v, off);
        if (ln == 0) atomicAdd(&spool[m], v);
    }
    __syncthreads();
    if (t < NKER)
        g_pooled[(size_t)(l * BATCH + b) * NKER + t] = spool[t];
}

// ---- final combine: out[b] = cls . W[:768] + kf . W[768:] + bias ----
__global__ void combine_kernel(const float* __restrict__ hs,
                               const float* __restrict__ W,
                               const float* __restrict__ bC,
                               float* __restrict__ out)
{
    __shared__ float red[128];
    int b = blockIdx.x, t = threadIdx.x;
    const float* cls = hs + (size_t)((L_LAYERS - 1) * BATCH + b) * SEQ * HID; // token 0
    float s = 0.f;
    for (int f = t; f < HID; f += 128)
        s = fmaf(cls[f], W[f], s);
    for (int f = t; f < (L_LAYERS + 1) * NKER; f += 128) {
        int la = f / NKER;
        int m  = f - la * NKER;
        int cl = (la == 0) ? 0 : la - 1;   // all_layers[0] == hidden_states[0]
        s = fmaf(g_pooled[(size_t)(cl * BATCH + b) * NKER + m], W[HID + f], s);
    }
    red[t] = s;
    __syncthreads();
    #pragma unroll
    for (int st = 64; st; st >>= 1) {
        if (t < st) red[t] += red[t + st];
        __syncthreads();
    }
    if (t == 0) out[b] = red[0] + bC[0];
}

extern "C" void kernel_launch(void* const* d_in, const int* in_sizes, int n_in,
                              void* d_out, int out_size)
{
    const float* hs = (const float*)d_in[0];
    const float* mu = (const float*)d_in[1];
    const float* sg = (const float*)d_in[2];
    const float* W  = (const float*)d_in[3];
    const float* bC = (const float*)d_in[4];
    float* out = (float*)d_out;

    cudaFuncSetAttribute(knrm_kernel,
                         cudaFuncAttributeMaxDynamicSharedMemorySize, SMEM_BYTES);

    dim3 grid(BATCH, L_LAYERS);
    knrm_kernel<<<grid, NTHR, SMEM_BYTES>>>(hs, mu, sg);
    combine_kernel<<<BATCH, 128>>>(hs, W, bC, out);
}

// round 8
// speedup vs baseline: 1.7370x; 1.2242x over previous
#include <cuda_runtime.h>
#include <cstdint>

#define L_LAYERS 13
#define BATCH    32
#define SEQ      512
#define HID      768
#define QLEN     20
#define DLEN     492          // SEQ - QLEN
#define NKER     11
#define EPS_N    1e-8f
#define NCTAS    (L_LAYERS * BATCH)   // 416

#define NTHR     512
#define NWARP    16
#define KC       16           // k-slice per stage
#define NSTAGE   (HID / KC)   // 48
#define NBUF     4            // per-warp ring depth
#define WROWS    32           // d-tokens per warp
#define DPAD     20           // padded row (floats); 16B-aligned rows, conflict-free frags
#define WBUF_ELT (WROWS * DPAD)          // 640 words per stage tile
#define WREG_ELT (NBUF * WBUF_ELT)       // 2560 words per warp region
#define KP       772          // Q row stride (772 mod 32 == 4 -> conflict-free A frags)
#define QROWS    20
#define QSM_ELT  (QROWS * KP)            // 15440 words
#define SMEM_BYTES ((QSM_ELT + NWARP * WREG_ELT) * 4)   // 225600 B

__device__ float g_pooled[L_LAYERS * BATCH * NKER];
__device__ unsigned int g_ctr;   // monotonic; (old % NCTAS)==NCTAS-1 -> last CTA

__device__ __forceinline__ uint32_t smaddr(const void* p) {
    uint32_t r;
    asm("{ .reg .u64 t; cvta.to.shared.u64 t, %1; cvt.u32.u64 %0, t; }"
        : "=r"(r) : "l"(p));
    return r;
}
__device__ __forceinline__ void cp16(uint32_t dst, const float* src) {
    asm volatile("cp.async.cg.shared.global [%0], [%1], 16;"
                 :: "r"(dst), "l"(__cvta_generic_to_global(src)));
}
__device__ __forceinline__ uint32_t f2tf32(float v) {
    uint32_t r;
    asm("cvt.rna.tf32.f32 %0, %1;" : "=r"(r) : "f"(v));
    return r;
}
__device__ __forceinline__ void mma_tf32(float* c, const uint32_t* a,
                                         uint32_t b0, uint32_t b1) {
    asm volatile(
        "mma.sync.aligned.m16n8k8.row.col.f32.tf32.tf32.f32 "
        "{%0,%1,%2,%3}, {%4,%5,%6,%7}, {%8,%9}, {%0,%1,%2,%3};"
        : "+f"(c[0]), "+f"(c[1]), "+f"(c[2]), "+f"(c[3])
        : "r"(a[0]), "r"(a[1]), "r"(a[2]), "r"(a[3]), "r"(b0), "r"(b1));
}

__global__ void __launch_bounds__(NTHR, 1)
knrm_kernel(const float* __restrict__ hs,
            const float* __restrict__ mu,
            const float* __restrict__ sigma,
            const float* __restrict__ W,
            const float* __restrict__ bC,
            float* __restrict__ out)
{
    extern __shared__ float sm[];
    uint32_t* qs   = (uint32_t*)sm;        // [QROWS][KP] tf32, row-major
    float*    dbuf = sm + QSM_ELT;         // [NWARP][NBUF][WROWS][DPAD]

    __shared__ float qinv[QLEN];
    __shared__ float mu_s[NKER], cf_s[NKER];
    __shared__ float spool[NKER];
    __shared__ int   do_combine;

    const int t  = threadIdx.x;
    const int b  = blockIdx.x;
    const int l  = blockIdx.y;
    const int ln = t & 31;
    const int w  = t >> 5;
    const int gr = ln >> 2;            // fragment group (0..7)
    const int c  = ln & 3;             // thread-in-group (0..3)
    const int wbase = w * WROWS;       // this warp's token base

    const float* base = hs + (size_t)(l * BATCH + b) * SEQ * HID;
    const float* qg   = base;              // tokens [0,20)
    const float* dg   = base + QLEN * HID; // tokens [20,512)

    float* warpbuf = dbuf + w * WREG_ELT;
    uint32_t wsm = smaddr(warpbuf);

    if (t < NKER) {
        mu_s[t] = mu[t];
        float sg = sigma[t];
        cf_s[t] = -0.5f / (sg * sg);
        spool[t] = 0.f;
    }
    if (t == 0) do_combine = 0;

    // ---- warp 15: zero its whole ring (rows for tokens >= 492 stay zero) ----
    if (w == NWARP - 1) {
        for (int i = ln; i < WREG_ELT; i += 32)
            warpbuf[i] = 0.f;
    }

    // ---- prologue: each warp prefetches its first NBUF stage tiles ----
    #pragma unroll
    for (int ps = 0; ps < NBUF; ps++) {
        int kg = ps * KC;
        #pragma unroll
        for (int i = 0; i < 4; i++) {
            int idx = ln + 32 * i;         // 0..127
            int row = idx >> 2;            // 0..31
            int kq  = idx & 3;             // 16B chunk
            int tok = wbase + row;
            if (tok < DLEN)
                cp16(wsm + (uint32_t)(ps * WBUF_ELT + row * DPAD + kq * 4) * 4,
                     dg + (size_t)tok * HID + kg + kq * 4);
        }
        asm volatile("cp.async.commit_group;");
    }

    // ---- stage Q -> tf32 row-major [QROWS][KP] ----
    for (int idx = t; idx < QROWS * (HID / 4); idx += NTHR) {
        int row = idx / (HID / 4);
        int k4  = idx % (HID / 4);
        float4 v = *(const float4*)(qg + row * HID + k4 * 4);
        uint32_t* dst = qs + row * KP + k4 * 4;
        dst[0] = f2tf32(v.x);
        dst[1] = f2tf32(v.y);
        dst[2] = f2tf32(v.z);
        dst[3] = f2tf32(v.w);
    }

    // ---- q inverse norms (exact fp32, from global) ----
    for (int r = w; r < QLEN; r += NWARP) {
        float s = 0.f;
        for (int k = ln; k < HID; k += 32) {
            float v = qg[r * HID + k];
            s = fmaf(v, v, s);
        }
        #pragma unroll
        for (int off = 16; off; off >>= 1)
            s += __shfl_down_sync(0xffffffffu, s, off);
        if (ln == 0) qinv[r] = 1.f / fmaxf(sqrtf(s), EPS_N);
    }
    __syncthreads();   // qs, qinv, mu_s/cf_s, spool visible; mainloop is barrier-free

    // ---- mainloop: warp-autonomous tf32 mma pipeline ----
    float acc[2][4][4];
    #pragma unroll
    for (int mt = 0; mt < 2; mt++)
        #pragma unroll
        for (int nt = 0; nt < 4; nt++)
            #pragma unroll
            for (int e = 0; e < 4; e++) acc[mt][nt][e] = 0.f;
    float ds[4];
    #pragma unroll
    for (int nt = 0; nt < 4; nt++) ds[nt] = 0.f;

    for (int s = 0; s < NSTAGE; s++) {
        // A fragments for both k8 steps (independent of D buffer; overlap the wait)
        uint32_t a0[2][4], a1[2][2];
        #pragma unroll
        for (int step = 0; step < 2; step++) {
            int kkc = s * KC + step * 8 + c;
            a0[step][0] = qs[ gr      * KP + kkc];
            a0[step][1] = qs[(gr + 8) * KP + kkc];
            a0[step][2] = qs[ gr      * KP + kkc + 4];
            a0[step][3] = qs[(gr + 8) * KP + kkc + 4];
            a1[step][0] = (gr < 4) ? qs[(16 + gr) * KP + kkc]     : 0u;
            a1[step][1] = (gr < 4) ? qs[(16 + gr) * KP + kkc + 4] : 0u;
        }

        asm volatile("cp.async.wait_group %0;" :: "n"(NBUF - 1));  // warp-local

        const float* db = warpbuf + (s & (NBUF - 1)) * WBUF_ELT;

        #pragma unroll
        for (int step = 0; step < 2; step++) {
            uint32_t afr1[4] = { a1[step][0], 0u, a1[step][1], 0u };
            #pragma unroll
            for (int nt = 0; nt < 4; nt++) {
                const float* dp = db + (nt * 8 + gr) * DPAD + step * 8;
                float f0 = dp[c];
                float f1 = dp[c + 4];
                ds[nt] = fmaf(f0, f0, fmaf(f1, f1, ds[nt]));
                uint32_t b0 = __float_as_uint(f0);   // tf32 by truncation
                uint32_t b1 = __float_as_uint(f1);
                mma_tf32(acc[0][nt], a0[step], b0, b1);
                mma_tf32(acc[1][nt], afr1,     b0, b1);
            }
        }

        // refill the slot just consumed with stage s+NBUF (warp-local, no barrier)
        if (s + NBUF < NSTAGE) {
            int kg = (s + NBUF) * KC;
            uint32_t dstb = wsm + (uint32_t)((s & (NBUF - 1)) * WBUF_ELT) * 4;
            #pragma unroll
            for (int i = 0; i < 4; i++) {
                int idx = ln + 32 * i;
                int row = idx >> 2;
                int kq  = idx & 3;
                int tok = wbase + row;
                if (tok < DLEN)
                    cp16(dstb + (uint32_t)(row * DPAD + kq * 4) * 4,
                         dg + (size_t)tok * HID + kg + kq * 4);
            }
        }
        asm volatile("cp.async.commit_group;");   // always (possibly empty) group
    }

    // ---- d inverse norms ----
    // ds[nt] is the partial norm of the token this thread LOADED (nt*8 + gr).
    // Quad xor-reduce over c leaves the full norm in all 4 lanes of the quad;
    // dinv[nt] then lives at lane 4*j for C-column token nt*8 + j.
    float dinv[4];
    #pragma unroll
    for (int nt = 0; nt < 4; nt++) {
        float v = ds[nt];
        v += __shfl_xor_sync(0xffffffffu, v, 1);
        v += __shfl_xor_sync(0xffffffffu, v, 2);
        dinv[nt] = 1.f / fmaxf(sqrtf(v), EPS_N);   // norm of token nt*8 + gr
    }
    // fetch the dinv for the C-fragment columns this thread owns: j = 2c, 2c+1
    float dv0[4], dv1[4];
    #pragma unroll
    for (int nt = 0; nt < 4; nt++) {
        dv0[nt] = __shfl_sync(0xffffffffu, dinv[nt], 8 * c);       // token nt*8 + 2c
        dv1[nt] = __shfl_sync(0xffffffffu, dinv[nt], 8 * c + 4);   // token nt*8 + 2c+1
    }

    // ---- Gaussian kernels + pooling ----
    float p[NKER];
    #pragma unroll
    for (int m = 0; m < NKER; m++) p[m] = 0.f;
    float mur[NKER], cfr[NKER];
    #pragma unroll
    for (int m = 0; m < NKER; m++) { mur[m] = mu_s[m]; cfr[m] = cf_s[m]; }

    #pragma unroll
    for (int mt = 0; mt < 2; mt++) {
        #pragma unroll
        for (int h = 0; h < 2; h++) {
            int m = mt * 16 + gr + h * 8;
            if (m < QLEN) {
                float qi = qinv[m];
                #pragma unroll
                for (int nt = 0; nt < 4; nt++) {
                    #pragma unroll
                    for (int col = 0; col < 2; col++) {
                        int tok = wbase + nt * 8 + 2 * c + col;
                        if (tok < DLEN) {
                            float di = (col == 0) ? dv0[nt] : dv1[nt];
                            float simv = acc[mt][nt][h * 2 + col] * qi * di;
                            #pragma unroll
                            for (int j = 0; j < NKER; j++) {
                                float dlt = simv - mur[j];
                                p[j] += __expf(cfr[j] * dlt * dlt);
                            }
                        }
                    }
                }
            }
        }
    }

    // warp reduce then smem atomic
    #pragma unroll
    for (int m = 0; m < NKER; m++) {
        float v = p[m];
        #pragma unroll
        for (int off = 16; off; off >>= 1)
            v += __shfl_down_sync(0xffffffffu, v, off);
        if (ln == 0) atomicAdd(&spool[m], v);
    }
    __syncthreads();
    if (t < NKER)
        g_pooled[(size_t)(l * BATCH + b) * NKER + t] = spool[t];

    // ---- last CTA performs the combine (saves a kernel launch) ----
    __syncthreads();
    if (t == 0) {
        __threadfence();
        unsigned int old = atomicAdd(&g_ctr, 1u);
        do_combine = ((old % (unsigned)NCTAS) == (unsigned)(NCTAS - 1)) ? 1 : 0;
    }
    __syncthreads();
    if (do_combine) {
        __threadfence();   // acquire: see all CTAs' g_pooled writes
        for (int bb = w; bb < BATCH; bb += NWARP) {
            const float* cls = hs + ((size_t)(L_LAYERS - 1) * BATCH + bb) * SEQ * HID;
            float s = 0.f;
            for (int f = ln; f < HID; f += 32)
                s = fmaf(cls[f], W[f], s);
            for (int f = ln; f < (L_LAYERS + 1) * NKER; f += 32) {
                int la = f / NKER;
                int m  = f - la * NKER;
                int cl = (la == 0) ? 0 : la - 1;   // all_layers[0] == hidden_states[0]
                s = fmaf(g_pooled[(size_t)(cl * BATCH + bb) * NKER + m], W[HID + f], s);
            }
            #pragma unroll
            for (int off = 16; off; off >>= 1)
                s += __shfl_down_sync(0xffffffffu, s, off);
            if (ln == 0) out[bb] = s + bC[0];
        }
    }
}

extern "C" void kernel_launch(void* const* d_in, const int* in_sizes, int n_in,
                              void* d_out, int out_size)
{
    const float* hs = (const float*)d_in[0];
    const float* mu = (const float*)d_in[1];
    const float* sg = (const float*)d_in[2];
    const float* W  = (const float*)d_in[3];
    const float* bC = (const float*)d_in[4];
    float* out = (float*)d_out;

    cudaFuncSetAttribute(knrm_kernel,
                         cudaFuncAttributeMaxDynamicSharedMemorySize, SMEM_BYTES);

    dim3 grid(BATCH, L_LAYERS);
    knrm_kernel<<<grid, NTHR, SMEM_BYTES>>>(hs, mu, sg, W, bC, out);
}